// round 9
// baseline (speedup 1.0000x reference)
#include <cuda_runtime.h>

#define NPTS   32768
#define GRIDSZ 16
#define CDIM   64
#define NVERT  (4 * GRIDSZ * GRIDSZ * GRIDSZ)   // 16384
#define CAP    256
#define VPB    4                                 // vertices per CTA
#define GTPB   128

__device__ int  g_cnt[NVERT];
__device__ int2 g_list[NVERT * CAP];            // (point_id, weight bits)

__global__ void zero_kernel(float4* __restrict__ out4, int nOut4) {
    int i = blockIdx.x * blockDim.x + threadIdx.x;
    if (i < NVERT) g_cnt[i] = 0;
    if (i < nOut4) out4[i] = make_float4(0.f, 0.f, 0.f, 0.f);
}

__global__ void bin_points_kernel(const int* __restrict__ pidx,
                                  const float* __restrict__ pos)
{
    int p = blockIdx.x * blockDim.x + threadIdx.x;
    if (p >= NPTS) return;

    const int k  = pidx[p];
    const float px = pos[p * 3 + 0] * GRIDSZ - 0.5f;
    const float py = pos[p * 3 + 1] * GRIDSZ - 0.5f;
    const float pz = pos[p * 3 + 2] * GRIDSZ - 0.5f;
    const float fx = floorf(px), fy = floorf(py), fz = floorf(pz);

    float wx[2], wy[2], wz[2];
    wx[1] = px - fx; wx[0] = 1.0f - wx[1];
    wy[1] = py - fy; wy[0] = 1.0f - wy[1];
    wz[1] = pz - fz; wz[0] = 1.0f - wz[1];

    int ix[2], iy[2], iz[2];
    ix[0] = min(max((int)fx,     0), GRIDSZ - 1);
    ix[1] = min(max((int)fx + 1, 0), GRIDSZ - 1);
    iy[0] = min(max((int)fy,     0), GRIDSZ - 1);
    iy[1] = min(max((int)fy + 1, 0), GRIDSZ - 1);
    iz[0] = min(max((int)fz,     0), GRIDSZ - 1);
    iz[1] = min(max((int)fz + 1, 0), GRIDSZ - 1);

    #pragma unroll
    for (int cz = 0; cz < 2; ++cz)
        #pragma unroll
        for (int cy = 0; cy < 2; ++cy)
            #pragma unroll
            for (int cx = 0; cx < 2; ++cx) {
                const float w = wz[cz] * wy[cy] * wx[cx];
                const int v = ((k * GRIDSZ + iz[cz]) * GRIDSZ + iy[cy]) * GRIDSZ + ix[cx];
                int slot = atomicAdd(&g_cnt[v], 1);
                if (slot < CAP)
                    g_list[v * CAP + slot] = make_int2(p, __float_as_int(w));
            }
}

__device__ __forceinline__ void red_add_v4(float* o, float4 v) {
    asm volatile("red.global.add.v4.f32 [%0], {%1,%2,%3,%4};"
                 :: "l"(o), "f"(v.x), "f"(v.y), "f"(v.z), "f"(v.w) : "memory");
}

__device__ __forceinline__ void cp_async16(unsigned smem_dst, const void* gptr) {
    asm volatile("cp.async.cg.shared.global [%0], [%1], 16;"
                 :: "r"(smem_dst), "l"(gptr));
}

__device__ __forceinline__ void fma4x4(float4& a, float4 x,
                                       float4 m0, float4 m1, float4 m2, float4 m3)
{
    a.x = fmaf(x.x, m0.x, a.x); a.y = fmaf(x.x, m0.y, a.y);
    a.z = fmaf(x.x, m0.z, a.z); a.w = fmaf(x.x, m0.w, a.w);
    a.x = fmaf(x.y, m1.x, a.x); a.y = fmaf(x.y, m1.y, a.y);
    a.z = fmaf(x.y, m1.z, a.z); a.w = fmaf(x.y, m1.w, a.w);
    a.x = fmaf(x.z, m2.x, a.x); a.y = fmaf(x.z, m2.y, a.y);
    a.z = fmaf(x.z, m2.z, a.z); a.w = fmaf(x.z, m2.w, a.w);
    a.x = fmaf(x.w, m3.x, a.x); a.y = fmaf(x.w, m3.y, a.y);
    a.z = fmaf(x.w, m3.z, a.z); a.w = fmaf(x.w, m3.w, a.w);
}

__global__ void __launch_bounds__(GTPB) gather_kernel(
    const float* __restrict__ K,     // [NVERT][64][64]
    const float* __restrict__ B,     // [NVERT][64]
    const float* __restrict__ xs,    // [N][64]
    float*       __restrict__ out)   // [N][64]
{
    __shared__ float4 sM[2][CDIM * 16];   // double-buffered matrix
    __shared__ float4 sXw[4][2][18];      // per-warp x staging (18 = pad, bank-offset 8)

    const int tid  = threadIdx.x;
    const int wid  = tid >> 5;
    const int lane = tid & 31;
    const int q    = lane & 15;   // channel quad (4 output channels)
    const int h    = lane >> 4;   // which point of the pair this lane owns
    const int v0   = blockIdx.x * VPB;

    int cnts[VPB];
    #pragma unroll
    for (int i = 0; i < VPB; ++i) {
        int c = __ldg(&g_cnt[v0 + i]);
        cnts[i] = (c > CAP) ? CAP : c;
    }

    // prefetch matrix for vertex 0 into buf 0
    {
        const float4* Kf4 = reinterpret_cast<const float4*>(K + (size_t)v0 * CDIM * CDIM);
        unsigned dst = (unsigned)__cvta_generic_to_shared(&sM[0][0]);
        #pragma unroll
        for (int j = 0; j < 8; ++j)
            cp_async16(dst + (unsigned)(tid + j * GTPB) * 16u, Kf4 + tid + j * GTPB);
        asm volatile("cp.async.commit_group;");
    }

    #pragma unroll 1
    for (int i = 0; i < VPB; ++i) {
        const int v   = v0 + i;
        const int cnt = cnts[i];
        const int buf = i & 1;

        __syncthreads();   // all reads of sM[buf^1] (prev vertex) done

        if (i + 1 < VPB) {
            const float4* Kn =
                reinterpret_cast<const float4*>(K + (size_t)(v + 1) * CDIM * CDIM);
            unsigned dst = (unsigned)__cvta_generic_to_shared(&sM[buf ^ 1][0]);
            #pragma unroll
            for (int j = 0; j < 8; ++j)
                cp_async16(dst + (unsigned)(tid + j * GTPB) * 16u, Kn + tid + j * GTPB);
        }
        asm volatile("cp.async.commit_group;");   // (empty group on last iter)

        const float4 bq = reinterpret_cast<const float4*>(B + (size_t)v * CDIM)[q];

        asm volatile("cp.async.wait_group 1;");
        __syncthreads();

        const float4* sMb = sM[buf];
        const int2*   lst = g_list + (size_t)v * CAP;

        const int s0 = 2 * wid;
        if (s0 < cnt) {
            // ---- pipeline prologue ----
            int2 e0 = make_int2(0, 0), e1 = make_int2(0, 0);
            if (lane < 2)              e0 = lst[s0 + lane];         // s0+1 <= 255: in-bounds
            if (lane < 2 && s0 + 8 < cnt) e1 = lst[s0 + 8 + lane];

            int   pid = __shfl_sync(0xffffffffu, e0.x, h);
            float w   = __int_as_float(__shfl_sync(0xffffffffu, e0.y, h));
            float4 xq = reinterpret_cast<const float4*>(xs + (size_t)pid * CDIM)[q];

            for (int s = s0; s < cnt; s += 8) {
                // list prefetch two pairs ahead
                int2 e2 = make_int2(0, 0);
                if (lane < 2 && s + 16 < cnt) e2 = lst[s + 16 + lane];

                __syncwarp();
                sXw[wid][h][q] = xq;
                __syncwarp();

                // next pair's pids + xs prefetch (latency hidden by compute)
                const int   pidn = __shfl_sync(0xffffffffu, e1.x, h);
                const float wn   = __int_as_float(__shfl_sync(0xffffffffu, e1.y, h));
                float4 xqn = make_float4(0.f, 0.f, 0.f, 0.f);
                if (s + 8 < cnt)
                    xqn = reinterpret_cast<const float4*>(xs + (size_t)pidn * CDIM)[q];

                float4 acc = make_float4(0.f, 0.f, 0.f, 0.f);
                #pragma unroll
                for (int c4 = 0; c4 < 16; ++c4) {
                    const float4 x  = sXw[wid][h][c4];
                    const float4 m0 = sMb[(4 * c4 + 0) * 16 + q];
                    const float4 m1 = sMb[(4 * c4 + 1) * 16 + q];
                    const float4 m2 = sMb[(4 * c4 + 2) * 16 + q];
                    const float4 m3 = sMb[(4 * c4 + 3) * 16 + q];
                    fma4x4(acc, x, m0, m1, m2, m3);
                }

                if (s + h < cnt) {
                    float* o = out + (size_t)pid * CDIM + 4 * q;
                    red_add_v4(o, make_float4(w * (acc.x + bq.x), w * (acc.y + bq.y),
                                              w * (acc.z + bq.z), w * (acc.w + bq.w)));
                }

                pid = pidn; w = wn; xq = xqn; e1 = e2;
            }
        }
    }
}

extern "C" void kernel_launch(void* const* d_in, const int* in_sizes, int n_in,
                              void* d_out, int out_size)
{
    const int*   pidx = (const int*)  d_in[0];
    const float* pos  = (const float*)d_in[1];
    const float* xs   = (const float*)d_in[2];
    const float* K    = (const float*)d_in[3];
    const float* B    = (const float*)d_in[4];
    float*       out  = (float*)d_out;

    const int nOut4 = out_size / 4;
    const int zN    = (nOut4 > NVERT ? nOut4 : NVERT);
    zero_kernel<<<(zN + 255) / 256, 256>>>((float4*)d_out, nOut4);
    bin_points_kernel<<<(NPTS + 127) / 128, 128>>>(pidx, pos);
    gather_kernel<<<NVERT / VPB, GTPB>>>(K, B, xs, out);
}

// round 10
// speedup vs baseline: 1.3366x; 1.3366x over previous
#include <cuda_runtime.h>

#define NPTS   32768
#define GRIDSZ 16
#define CDIM   64
#define NVERT  (4 * GRIDSZ * GRIDSZ * GRIDSZ)   // 16384
#define CAP    256
#define VPB    4                                 // vertices per CTA
#define GTPB   128

__device__ int  g_cnt[NVERT];
__device__ int2 g_list[NVERT * CAP];            // (point_id, weight bits)

__global__ void zero_kernel(float4* __restrict__ out4, int nOut4) {
    int i = blockIdx.x * blockDim.x + threadIdx.x;
    if (i < NVERT) g_cnt[i] = 0;
    if (i < nOut4) out4[i] = make_float4(0.f, 0.f, 0.f, 0.f);
}

__global__ void bin_points_kernel(const int* __restrict__ pidx,
                                  const float* __restrict__ pos)
{
    int p = blockIdx.x * blockDim.x + threadIdx.x;
    if (p >= NPTS) return;

    const int k  = pidx[p];
    const float px = pos[p * 3 + 0] * GRIDSZ - 0.5f;
    const float py = pos[p * 3 + 1] * GRIDSZ - 0.5f;
    const float pz = pos[p * 3 + 2] * GRIDSZ - 0.5f;
    const float fx = floorf(px), fy = floorf(py), fz = floorf(pz);

    float wx[2], wy[2], wz[2];
    wx[1] = px - fx; wx[0] = 1.0f - wx[1];
    wy[1] = py - fy; wy[0] = 1.0f - wy[1];
    wz[1] = pz - fz; wz[0] = 1.0f - wz[1];

    int ix[2], iy[2], iz[2];
    ix[0] = min(max((int)fx,     0), GRIDSZ - 1);
    ix[1] = min(max((int)fx + 1, 0), GRIDSZ - 1);
    iy[0] = min(max((int)fy,     0), GRIDSZ - 1);
    iy[1] = min(max((int)fy + 1, 0), GRIDSZ - 1);
    iz[0] = min(max((int)fz,     0), GRIDSZ - 1);
    iz[1] = min(max((int)fz + 1, 0), GRIDSZ - 1);

    #pragma unroll
    for (int cz = 0; cz < 2; ++cz)
        #pragma unroll
        for (int cy = 0; cy < 2; ++cy)
            #pragma unroll
            for (int cx = 0; cx < 2; ++cx) {
                const float w = wz[cz] * wy[cy] * wx[cx];
                const int v = ((k * GRIDSZ + iz[cz]) * GRIDSZ + iy[cy]) * GRIDSZ + ix[cx];
                int slot = atomicAdd(&g_cnt[v], 1);
                if (slot < CAP)
                    g_list[v * CAP + slot] = make_int2(p, __float_as_int(w));
            }
}

__device__ __forceinline__ void red_add_v4(float* o, float4 v) {
    asm volatile("red.global.add.v4.f32 [%0], {%1,%2,%3,%4};"
                 :: "l"(o), "f"(v.x), "f"(v.y), "f"(v.z), "f"(v.w) : "memory");
}

__device__ __forceinline__ void cp_async16(unsigned smem_dst, const void* gptr) {
    asm volatile("cp.async.cg.shared.global [%0], [%1], 16;"
                 :: "r"(smem_dst), "l"(gptr));
}

__device__ __forceinline__ void fma4x4(float4& a, float4 x,
                                       float4 m0, float4 m1, float4 m2, float4 m3)
{
    a.x = fmaf(x.x, m0.x, a.x); a.y = fmaf(x.x, m0.y, a.y);
    a.z = fmaf(x.x, m0.z, a.z); a.w = fmaf(x.x, m0.w, a.w);
    a.x = fmaf(x.y, m1.x, a.x); a.y = fmaf(x.y, m1.y, a.y);
    a.z = fmaf(x.y, m1.z, a.z); a.w = fmaf(x.y, m1.w, a.w);
    a.x = fmaf(x.z, m2.x, a.x); a.y = fmaf(x.z, m2.y, a.y);
    a.z = fmaf(x.z, m2.z, a.z); a.w = fmaf(x.z, m2.w, a.w);
    a.x = fmaf(x.w, m3.x, a.x); a.y = fmaf(x.w, m3.y, a.y);
    a.z = fmaf(x.w, m3.z, a.z); a.w = fmaf(x.w, m3.w, a.w);
}

__global__ void __launch_bounds__(GTPB) gather_kernel(
    const float* __restrict__ K,     // [NVERT][64][64]
    const float* __restrict__ B,     // [NVERT][64]
    const float* __restrict__ xs,    // [N][64]
    float*       __restrict__ out)   // [N][64]
{
    __shared__ float4 sM[2][CDIM * 16];  // double-buffered matrix
    __shared__ float  sX[16][CDIM];      // x rows; warp w touches rows {2w,2w+1,2w+8,2w+9} only

    const int tid  = threadIdx.x;
    const int wid  = tid >> 5;
    const int lane = tid & 31;
    const int q    = lane & 15;   // channel quad
    const int hh   = lane >> 4;   // 0/1: which row of the pair
    const int gA   = 2 * wid + hh;      // acc0 row
    const int gB   = gA + 8;            // acc1 row
    const int v0   = blockIdx.x * VPB;

    int cnts[VPB];
    #pragma unroll
    for (int i = 0; i < VPB; ++i) {
        int c = __ldg(&g_cnt[v0 + i]);
        cnts[i] = (c > CAP) ? CAP : c;
    }

    {   // prefetch matrix for vertex 0 into buf 0
        const float4* Kf4 = reinterpret_cast<const float4*>(K + (size_t)v0 * CDIM * CDIM);
        unsigned dst = (unsigned)__cvta_generic_to_shared(&sM[0][0]);
        #pragma unroll
        for (int j = 0; j < 8; ++j)
            cp_async16(dst + (unsigned)(tid + j * GTPB) * 16u, Kf4 + tid + j * GTPB);
        asm volatile("cp.async.commit_group;");
    }

    #pragma unroll 1
    for (int i = 0; i < VPB; ++i) {
        const int v   = v0 + i;
        const int cnt = cnts[i];
        const int buf = i & 1;

        __syncthreads();   // prev vertex's reads of sM[buf^1] complete

        if (i + 1 < VPB) {
            const float4* Kn =
                reinterpret_cast<const float4*>(K + (size_t)(v + 1) * CDIM * CDIM);
            unsigned dst = (unsigned)__cvta_generic_to_shared(&sM[buf ^ 1][0]);
            #pragma unroll
            for (int j = 0; j < 8; ++j)
                cp_async16(dst + (unsigned)(tid + j * GTPB) * 16u, Kn + tid + j * GTPB);
        }
        asm volatile("cp.async.commit_group;");

        const float4 bq = reinterpret_cast<const float4*>(B + (size_t)v * CDIM)[q];
        const int2*  lst = g_list + (size_t)v * CAP;

        // prefetch chunk-0 list entries (redundant per warp; lanes 0..15)
        int2 e = make_int2(0, 0);
        if (lane < 16) e = lst[lane];          // always in-bounds (<= 255)

        asm volatile("cp.async.wait_group 1;"); // matrix for vertex i landed
        __syncthreads();

        const float4* sMb = sM[buf];
        const int s0 = 2 * wid;

        // -------- warp-autonomous mainloop: NO block barriers --------
        for (int s = s0; s < cnt; s += 16) {
            // this pass's pids/weights via shfl from the chunk entries
            const int   pidA = __shfl_sync(0xffffffffu, e.x, 2 * wid + hh);
            const float wA   = __int_as_float(__shfl_sync(0xffffffffu, e.y, 2 * wid + hh));
            const int   pidB = __shfl_sync(0xffffffffu, e.x, 2 * wid + 8 + hh);
            const float wB   = __int_as_float(__shfl_sync(0xffffffffu, e.y, 2 * wid + 8 + hh));

            const bool doB = (s + 8 < cnt);     // warp-uniform

            // stage x rows (stale pids load harmless in-bounds data)
            reinterpret_cast<float4*>(sX[gA])[q] =
                reinterpret_cast<const float4*>(xs + (size_t)pidA * CDIM)[q];
            if (doB)
                reinterpret_cast<float4*>(sX[gB])[q] =
                    reinterpret_cast<const float4*>(xs + (size_t)pidB * CDIM)[q];
            __syncwarp();

            // prefetch next chunk's list entries during compute
            if (lane < 16 && s + 16 < cnt) e = lst[(s - s0) + 16 + lane];

            float4 a0 = make_float4(0.f, 0.f, 0.f, 0.f);
            float4 a1 = make_float4(0.f, 0.f, 0.f, 0.f);

            if (doB) {
                #pragma unroll
                for (int c4 = 0; c4 < 16; ++c4) {
                    const float4 x0 = reinterpret_cast<const float4*>(sX[gA])[c4];
                    const float4 x1 = reinterpret_cast<const float4*>(sX[gB])[c4];
                    const float4 m0 = sMb[(4 * c4 + 0) * 16 + q];
                    const float4 m1 = sMb[(4 * c4 + 1) * 16 + q];
                    const float4 m2 = sMb[(4 * c4 + 2) * 16 + q];
                    const float4 m3 = sMb[(4 * c4 + 3) * 16 + q];
                    fma4x4(a0, x0, m0, m1, m2, m3);
                    fma4x4(a1, x1, m0, m1, m2, m3);
                }
            } else {
                #pragma unroll
                for (int c4 = 0; c4 < 16; ++c4) {
                    const float4 x0 = reinterpret_cast<const float4*>(sX[gA])[c4];
                    const float4 m0 = sMb[(4 * c4 + 0) * 16 + q];
                    const float4 m1 = sMb[(4 * c4 + 1) * 16 + q];
                    const float4 m2 = sMb[(4 * c4 + 2) * 16 + q];
                    const float4 m3 = sMb[(4 * c4 + 3) * 16 + q];
                    fma4x4(a0, x0, m0, m1, m2, m3);
                }
            }
            __syncwarp();   // all reads of sX rows done before next pass overwrites

            if (s + hh < cnt) {
                float* o = out + (size_t)pidA * CDIM + 4 * q;
                red_add_v4(o, make_float4(wA * (a0.x + bq.x), wA * (a0.y + bq.y),
                                          wA * (a0.z + bq.z), wA * (a0.w + bq.w)));
            }
            if (doB && (s + 8 + hh < cnt)) {
                float* o = out + (size_t)pidB * CDIM + 4 * q;
                red_add_v4(o, make_float4(wB * (a1.x + bq.x), wB * (a1.y + bq.y),
                                          wB * (a1.z + bq.z), wB * (a1.w + bq.w)));
            }
        }
    }
}

extern "C" void kernel_launch(void* const* d_in, const int* in_sizes, int n_in,
                              void* d_out, int out_size)
{
    const int*   pidx = (const int*)  d_in[0];
    const float* pos  = (const float*)d_in[1];
    const float* xs   = (const float*)d_in[2];
    const float* K    = (const float*)d_in[3];
    const float* B    = (const float*)d_in[4];
    float*       out  = (float*)d_out;

    const int nOut4 = out_size / 4;
    const int zN    = (nOut4 > NVERT ? nOut4 : NVERT);
    zero_kernel<<<(zN + 255) / 256, 256>>>((float4*)d_out, nOut4);
    bin_points_kernel<<<(NPTS + 127) / 128, 128>>>(pidx, pos);
    gather_kernel<<<NVERT / VPB, GTPB>>>(K, B, xs, out);
}

// round 12
// speedup vs baseline: 1.3613x; 1.0185x over previous
#include <cuda_runtime.h>

#define NPTS   32768
#define GRIDSZ 16
#define CDIM   64
#define NVERT  (4 * GRIDSZ * GRIDSZ * GRIDSZ)   // 16384
#define CAP    256
#define VPB    4                                 // vertices per CTA
#define GTPB   128

__device__ int  g_cnt[NVERT];    // zero at load; gather resets after reading -> replay-safe
__device__ int2 g_list[NVERT * CAP];            // (point_id, weight bits)

// fused: bin points + zero output buffer (2-launch graph)
__global__ void bin_zero_kernel(const int* __restrict__ pidx,
                                const float* __restrict__ pos,
                                float4* __restrict__ out4, int nOut4)
{
    const int p = blockIdx.x * blockDim.x + threadIdx.x;   // 0..32767

    const float4 z = make_float4(0.f, 0.f, 0.f, 0.f);
    for (int i = p; i < nOut4; i += NPTS) out4[i] = z;

    if (p >= NPTS) return;

    const int k  = pidx[p];
    const float px = pos[p * 3 + 0] * GRIDSZ - 0.5f;
    const float py = pos[p * 3 + 1] * GRIDSZ - 0.5f;
    const float pz = pos[p * 3 + 2] * GRIDSZ - 0.5f;
    const float fx = floorf(px), fy = floorf(py), fz = floorf(pz);

    float wx[2], wy[2], wz[2];
    wx[1] = px - fx; wx[0] = 1.0f - wx[1];
    wy[1] = py - fy; wy[0] = 1.0f - wy[1];
    wz[1] = pz - fz; wz[0] = 1.0f - wz[1];

    int ix[2], iy[2], iz[2];
    ix[0] = min(max((int)fx,     0), GRIDSZ - 1);
    ix[1] = min(max((int)fx + 1, 0), GRIDSZ - 1);
    iy[0] = min(max((int)fy,     0), GRIDSZ - 1);
    iy[1] = min(max((int)fy + 1, 0), GRIDSZ - 1);
    iz[0] = min(max((int)fz,     0), GRIDSZ - 1);
    iz[1] = min(max((int)fz + 1, 0), GRIDSZ - 1);

    #pragma unroll
    for (int cz = 0; cz < 2; ++cz)
        #pragma unroll
        for (int cy = 0; cy < 2; ++cy)
            #pragma unroll
            for (int cx = 0; cx < 2; ++cx) {
                const float w = wz[cz] * wy[cy] * wx[cx];
                const int v = ((k * GRIDSZ + iz[cz]) * GRIDSZ + iy[cy]) * GRIDSZ + ix[cx];
                int slot = atomicAdd(&g_cnt[v], 1);
                if (slot < CAP)
                    g_list[v * CAP + slot] = make_int2(p, __float_as_int(w));
            }
}

__device__ __forceinline__ void red_add_v4(float* o, float4 v) {
    asm volatile("red.global.add.v4.f32 [%0], {%1,%2,%3,%4};"
                 :: "l"(o), "f"(v.x), "f"(v.y), "f"(v.z), "f"(v.w) : "memory");
}

__device__ __forceinline__ void cp_async16(unsigned smem_dst, const void* gptr) {
    asm volatile("cp.async.cg.shared.global [%0], [%1], 16;"
                 :: "r"(smem_dst), "l"(gptr));
}

__device__ __forceinline__ void fma4x4(float4& a, float4 x,
                                       float4 m0, float4 m1, float4 m2, float4 m3)
{
    a.x = fmaf(x.x, m0.x, a.x); a.y = fmaf(x.x, m0.y, a.y);
    a.z = fmaf(x.x, m0.z, a.z); a.w = fmaf(x.x, m0.w, a.w);
    a.x = fmaf(x.y, m1.x, a.x); a.y = fmaf(x.y, m1.y, a.y);
    a.z = fmaf(x.y, m1.z, a.z); a.w = fmaf(x.y, m1.w, a.w);
    a.x = fmaf(x.z, m2.x, a.x); a.y = fmaf(x.z, m2.y, a.y);
    a.z = fmaf(x.z, m2.z, a.z); a.w = fmaf(x.z, m2.w, a.w);
    a.x = fmaf(x.w, m3.x, a.x); a.y = fmaf(x.w, m3.y, a.y);
    a.z = fmaf(x.w, m3.z, a.z); a.w = fmaf(x.w, m3.w, a.w);
}

__global__ void __launch_bounds__(GTPB) gather_kernel(
    const float* __restrict__ K,     // [NVERT][64][64]
    const float* __restrict__ B,     // [NVERT][64]
    const float* __restrict__ xs,    // [N][64]
    float*       __restrict__ out)   // [N][64]
{
    __shared__ float4 sM[2][CDIM * 16];  // double-buffered matrix
    __shared__ float  sX[16][CDIM];      // warp w owns rows {2w,2w+1,2w+8,2w+9}

    const int tid  = threadIdx.x;
    const int wid  = tid >> 5;
    const int lane = tid & 31;
    const int q    = lane & 15;   // channel quad
    const int hh   = lane >> 4;   // 0/1: which row of the pair
    const int gA   = 2 * wid + hh;
    const int gB   = gA + 8;
    const int v0   = blockIdx.x * VPB;

    int cnts[VPB];
    #pragma unroll
    for (int i = 0; i < VPB; ++i) {
        int c = __ldg(&g_cnt[v0 + i]);
        cnts[i] = (c > CAP) ? CAP : c;
    }
    __syncthreads();                      // ALL reads complete before reset (R11 bug fix)
    if (tid < VPB) g_cnt[v0 + tid] = 0;   // replay invariant: counters return to 0

    {   // prefetch matrix for vertex 0 into buf 0
        const float4* Kf4 = reinterpret_cast<const float4*>(K + (size_t)v0 * CDIM * CDIM);
        unsigned dst = (unsigned)__cvta_generic_to_shared(&sM[0][0]);
        #pragma unroll
        for (int j = 0; j < 8; ++j)
            cp_async16(dst + (unsigned)(tid + j * GTPB) * 16u, Kf4 + tid + j * GTPB);
        asm volatile("cp.async.commit_group;");
    }

    #pragma unroll 1
    for (int i = 0; i < VPB; ++i) {
        const int v   = v0 + i;
        const int cnt = cnts[i];
        const int buf = i & 1;

        __syncthreads();   // prev vertex's reads of sM[buf^1] complete

        if (i + 1 < VPB) {
            const float4* Kn =
                reinterpret_cast<const float4*>(K + (size_t)(v + 1) * CDIM * CDIM);
            unsigned dst = (unsigned)__cvta_generic_to_shared(&sM[buf ^ 1][0]);
            #pragma unroll
            for (int j = 0; j < 8; ++j)
                cp_async16(dst + (unsigned)(tid + j * GTPB) * 16u, Kn + tid + j * GTPB);
        }
        asm volatile("cp.async.commit_group;");

        const float4 bq = reinterpret_cast<const float4*>(B + (size_t)v * CDIM)[q];
        const int2*  lst = g_list + (size_t)v * CAP;
        const int    s0  = 2 * wid;

        // ---- pipeline prologue: chunk-0 list, this pass's pids + xs, chunk-1 list ----
        int2 e = make_int2(0, 0);
        if (lane < 16) e = lst[lane];

        int   pidA = __shfl_sync(0xffffffffu, e.x, 2 * wid + hh);
        float wA   = __int_as_float(__shfl_sync(0xffffffffu, e.y, 2 * wid + hh));
        int   pidB = __shfl_sync(0xffffffffu, e.x, 2 * wid + 8 + hh);
        float wB   = __int_as_float(__shfl_sync(0xffffffffu, e.y, 2 * wid + 8 + hh));

        float4 xqA = make_float4(0.f, 0.f, 0.f, 0.f);
        float4 xqB = make_float4(0.f, 0.f, 0.f, 0.f);
        if (s0 < cnt) {
            xqA = reinterpret_cast<const float4*>(xs + (size_t)pidA * CDIM)[q];
            if (s0 + 8 < cnt)
                xqB = reinterpret_cast<const float4*>(xs + (size_t)pidB * CDIM)[q];
        }
        if (lane < 16 && s0 + 16 < cnt) e = lst[16 + lane];   // chunk 1

        asm volatile("cp.async.wait_group 1;");   // matrix for vertex i landed
        __syncthreads();

        const float4* sMb = sM[buf];

        // -------- warp-autonomous mainloop: no block barriers --------
        for (int s = s0; s < cnt; s += 16) {
            const bool doB = (s + 8 < cnt);       // warp-uniform

            reinterpret_cast<float4*>(sX[gA])[q] = xqA;
            if (doB) reinterpret_cast<float4*>(sX[gB])[q] = xqB;
            __syncwarp();

            // next pass's ids + xs prefetch; list prefetch two chunks ahead
            const int   pidA2 = __shfl_sync(0xffffffffu, e.x, 2 * wid + hh);
            const float wA2   = __int_as_float(__shfl_sync(0xffffffffu, e.y, 2 * wid + hh));
            const int   pidB2 = __shfl_sync(0xffffffffu, e.x, 2 * wid + 8 + hh);
            const float wB2   = __int_as_float(__shfl_sync(0xffffffffu, e.y, 2 * wid + 8 + hh));

            float4 xqA2 = make_float4(0.f, 0.f, 0.f, 0.f);
            float4 xqB2 = make_float4(0.f, 0.f, 0.f, 0.f);
            if (s + 16 < cnt) {
                xqA2 = reinterpret_cast<const float4*>(xs + (size_t)pidA2 * CDIM)[q];
                if (s + 24 < cnt)
                    xqB2 = reinterpret_cast<const float4*>(xs + (size_t)pidB2 * CDIM)[q];
            }
            int2 e2 = e;
            {
                const int idx = (s - s0) + 32 + lane;
                if (lane < 16 && s + 32 < cnt && idx < CAP) e2 = lst[idx];  // OOB fix
            }

            float4 a0 = make_float4(0.f, 0.f, 0.f, 0.f);
            float4 a1 = make_float4(0.f, 0.f, 0.f, 0.f);

            if (doB) {
                #pragma unroll
                for (int c4 = 0; c4 < 16; ++c4) {
                    const float4 x0 = reinterpret_cast<const float4*>(sX[gA])[c4];
                    const float4 x1 = reinterpret_cast<const float4*>(sX[gB])[c4];
                    const float4 m0 = sMb[(4 * c4 + 0) * 16 + q];
                    const float4 m1 = sMb[(4 * c4 + 1) * 16 + q];
                    const float4 m2 = sMb[(4 * c4 + 2) * 16 + q];
                    const float4 m3 = sMb[(4 * c4 + 3) * 16 + q];
                    fma4x4(a0, x0, m0, m1, m2, m3);
                    fma4x4(a1, x1, m0, m1, m2, m3);
                }
            } else {
                #pragma unroll
                for (int c4 = 0; c4 < 16; ++c4) {
                    const float4 x0 = reinterpret_cast<const float4*>(sX[gA])[c4];
                    const float4 m0 = sMb[(4 * c4 + 0) * 16 + q];
                    const float4 m1 = sMb[(4 * c4 + 1) * 16 + q];
                    const float4 m2 = sMb[(4 * c4 + 2) * 16 + q];
                    const float4 m3 = sMb[(4 * c4 + 3) * 16 + q];
                    fma4x4(a0, x0, m0, m1, m2, m3);
                }
            }
            __syncwarp();   // sX reads done before next pass overwrites

            if (s + hh < cnt) {
                float* o = out + (size_t)pidA * CDIM + 4 * q;
                red_add_v4(o, make_float4(wA * (a0.x + bq.x), wA * (a0.y + bq.y),
                                          wA * (a0.z + bq.z), wA * (a0.w + bq.w)));
            }
            if (doB && (s + 8 + hh < cnt)) {
                float* o = out + (size_t)pidB * CDIM + 4 * q;
                red_add_v4(o, make_float4(wB * (a1.x + bq.x), wB * (a1.y + bq.y),
                                          wB * (a1.z + bq.z), wB * (a1.w + bq.w)));
            }

            pidA = pidA2; wA = wA2; xqA = xqA2;
            pidB = pidB2; wB = wB2; xqB = xqB2;
            e = e2;
        }
    }
}

extern "C" void kernel_launch(void* const* d_in, const int* in_sizes, int n_in,
                              void* d_out, int out_size)
{
    const int*   pidx = (const int*)  d_in[0];
    const float* pos  = (const float*)d_in[1];
    const float* xs   = (const float*)d_in[2];
    const float* K    = (const float*)d_in[3];
    const float* B    = (const float*)d_in[4];
    float*       out  = (float*)d_out;

    const int nOut4 = out_size / 4;
    bin_zero_kernel<<<NPTS / 256, 256>>>(pidx, pos, (float4*)d_out, nOut4);
    gather_kernel<<<NVERT / VPB, GTPB>>>(K, B, xs, out);
}